// round 9
// baseline (speedup 1.0000x reference)
#include <cuda_runtime.h>

// Problem constants
#define Bn 4
#define Ln 2048
#define Dn 256
#define SLOTS 64
#define ROWS 192          // SLOTS * 3
#define MEMROWS 193       // + base row (row 192 = sum of all n=0 rows)
#define MPAD 260          // padded stride (words): conflict-free LDS.128
#define TILE 56           // 4 * 37 = 148 blocks = one full wave
#define CH 8              // positions per chunk
#define NT 512            // 16 warps: 6 GEMM + 10 gather in phase B
#define TILES_PER_B 37

// smem layout (words)
#define OFF_GSM  (MEMROWS * MPAD)             // 50180 : gsm[8][192]  K-half 0
#define OFF_PART (OFF_GSM + CH * ROWS)        // +1536 : part[8][192] K-half 1
#define OFF_HEAD (OFF_PART + CH * ROWS)       // +1536 : head[2][2][192]
#define OFF_BIAS (OFF_HEAD + 2 * 2 * ROWS)    // +768
#define OFF_BEST (OFF_BIAS + ROWS)            // +192  : best[8][64] compacted offsets
#define OFF_CNT  (OFF_BEST + CH * SLOTS)      // +512  : cnt[8][2]
#define OFF_XS   (OFF_CNT + 16)               // +16   : xs[8][256]
#define SMEM_WORDS (OFF_XS + CH * Dn)         // +2048 -> 56788 words = 227152 B

typedef unsigned long long u64;

__device__ __forceinline__ u64 fma2(u64 a, u64 b, u64 c) {
    u64 d;
    asm("fma.rn.f32x2 %0, %1, %2, %3;" : "=l"(d) : "l"(a), "l"(b), "l"(c));
    return d;
}
__device__ __forceinline__ u64 add2(u64 a, u64 b) {
    u64 d;
    asm("add.rn.f32x2 %0, %1, %2;" : "=l"(d) : "l"(a), "l"(b));
    return d;
}
__device__ __forceinline__ float hsum2(u64 a) {
    float lo, hi;
    asm("mov.b64 {%0,%1}, %2;" : "=f"(lo), "=f"(hi) : "l"(a));
    return lo + hi;
}

// GEMM slice: 2 columns (j0, j0+96), half-K (32 d4), 8 rows. x via broadcast LDS.
// (rows n>=1 of mem_s hold deltas; GEMM just dots rows, unchanged)
__device__ __forceinline__ void gemm_chunk(
    const float* __restrict__ xs,
    const ulonglong2* __restrict__ mp0,
    const ulonglong2* __restrict__ mp1,
    float* __restrict__ gdst, int d4b, int j0)
{
    const ulonglong2* xp = (const ulonglong2*)xs;
    u64 a0[8], a1[8];
    #pragma unroll
    for (int r = 0; r < 8; r++) { a0[r] = 0ULL; a1[r] = 0ULL; }
    #pragma unroll 4
    for (int d4 = d4b; d4 < d4b + 32; ++d4) {
        ulonglong2 m0 = mp0[d4];
        ulonglong2 m1 = mp1[d4];
        #pragma unroll
        for (int r = 0; r < 8; r++) {
            ulonglong2 xv = xp[r * 64 + d4];   // warp-uniform broadcast LDS.128
            a0[r] = fma2(m0.x, xv.x, a0[r]);
            a0[r] = fma2(m0.y, xv.y, a0[r]);
            a1[r] = fma2(m1.x, xv.x, a1[r]);
            a1[r] = fma2(m1.y, xv.y, a1[r]);
        }
    }
    #pragma unroll
    for (int r = 0; r < 8; r++) {
        gdst[r * ROWS + j0]      = hsum2(a0[r]);
        gdst[r * ROWS + j0 + 96] = hsum2(a1[r]);
    }
}

// gather one (p, d4) item: out = base_row + sum of compacted delta rows
__device__ __forceinline__ void gather_one(
    const float* __restrict__ mem_s, const int* __restrict__ best_s,
    const int* __restrict__ cnt_s,
    float* __restrict__ out, size_t orow, int it)
{
    int p = it >> 6, d4 = it & 63;
    ulonglong2 bv = ((const ulonglong2*)(mem_s + 192 * MPAD))[d4];  // base row
    u64 ax[4] = {bv.x, 0ULL, 0ULL, 0ULL};
    u64 ay[4] = {bv.y, 0ULL, 0ULL, 0ULL};
    #pragma unroll
    for (int h = 0; h < 2; h++) {
        int c = cnt_s[p * 2 + h];              // warp-uniform scalar LDS
        const int* lst = best_s + p * SLOTS + h * 32;
        int i = 0;
        for (; i + 4 <= c; i += 4) {
            int4 r4 = *(const int4*)(lst + i); // warp-uniform int4 broadcast
            int q = (i >> 2) & 3;
            ulonglong2 v;
            v = ((const ulonglong2*)(mem_s + r4.x))[d4];
            ax[q] = add2(ax[q], v.x); ay[q] = add2(ay[q], v.y);
            v = ((const ulonglong2*)(mem_s + r4.y))[d4];
            ax[q] = add2(ax[q], v.x); ay[q] = add2(ay[q], v.y);
            v = ((const ulonglong2*)(mem_s + r4.z))[d4];
            ax[q] = add2(ax[q], v.x); ay[q] = add2(ay[q], v.y);
            v = ((const ulonglong2*)(mem_s + r4.w))[d4];
            ax[q] = add2(ax[q], v.x); ay[q] = add2(ay[q], v.y);
        }
        for (; i < c; i++) {
            int off = lst[i];
            int q = i & 3;
            ulonglong2 v = ((const ulonglong2*)(mem_s + off))[d4];
            ax[q] = add2(ax[q], v.x); ay[q] = add2(ay[q], v.y);
        }
    }
    u64 s0 = add2(add2(ax[0], ax[1]), add2(ax[2], ax[3]));
    u64 s1 = add2(add2(ay[0], ay[1]), add2(ay[2], ay[3]));
    float x0, x1, y0, y1;
    asm("mov.b64 {%0,%1}, %2;" : "=f"(x0), "=f"(x1) : "l"(s0));
    asm("mov.b64 {%0,%1}, %2;" : "=f"(y0), "=f"(y1) : "l"(s1));
    ((float4*)(out + (orow + p) * Dn))[d4] = make_float4(x0, x1, y0, y1);
}

__global__ void __launch_bounds__(NT, 1)
pnm_kernel(const float* __restrict__ x,
           const float* __restrict__ mem,
           const float* __restrict__ bias,
           float* __restrict__ out)
{
    extern __shared__ float smem[];
    float* mem_s  = smem;                     // [MEMROWS][MPAD] (n>=1 rows = deltas)
    float* gsm    = smem + OFF_GSM;           // [8][192]
    float* part   = smem + OFF_PART;          // [8][192]
    float* head   = smem + OFF_HEAD;          // [2][2][192] (combined G values)
    float* bias_s = smem + OFF_BIAS;          // [192]
    int*   best_s = (int*)(smem + OFF_BEST);  // [8][64]
    int*   cnt_s  = (int*)(smem + OFF_CNT);   // [8][2]
    float* xs     = smem + OFF_XS;            // [8][256]

    const int tid  = threadIdx.x;
    const int b    = blockIdx.x / TILES_PER_B;
    const int l0   = (blockIdx.x % TILES_PER_B) * TILE;
    const int lend = (l0 + TILE < Ln) ? (l0 + TILE) : Ln;
    const int nc   = (lend - l0) / CH;        // 7 or 4

    const float* xb = x + (size_t)b * Ln * Dn;
    const size_t orow0 = (size_t)b * Ln;

    // ---- stage raw memory + bias + x chunk 0 ----
    for (int i = tid; i < ROWS * (Dn / 4); i += NT) {
        int r = i >> 6, c = i & 63;
        ((float4*)(mem_s + r * MPAD))[c] = ((const float4*)mem)[i];
    }
    if (tid < ROWS) bias_s[tid] = bias[tid];
    for (int i = tid; i < CH * (Dn / 4); i += NT) {
        int r = i >> 6, c = i & 63;
        ((float4*)(xs + r * Dn))[c] =
            ((const float4*)(xb + (size_t)(l0 + r) * Dn))[c];
    }
    __syncthreads();

    // ---- build base row (192) and convert n>=1 rows to deltas ----
    if (tid < 64) {   // base[d4] = sum over m of mem_s[m*3][d4]
        float4 s = make_float4(0.f, 0.f, 0.f, 0.f);
        for (int m = 0; m < SLOTS; m++) {
            float4 v = ((const float4*)(mem_s + (m * 3) * MPAD))[tid];
            s.x += v.x; s.y += v.y; s.z += v.z; s.w += v.w;
        }
        ((float4*)(mem_s + 192 * MPAD))[tid] = s;
    }
    for (int i = tid; i < 128 * (Dn / 4); i += NT) {
        int rr = i >> 6, c = i & 63;
        int m = rr >> 1, n = (rr & 1) + 1;
        float4 v  = ((const float4*)(mem_s + (m * 3 + n) * MPAD))[c];
        float4 b0 = ((const float4*)(mem_s + (m * 3) * MPAD))[c];
        v.x -= b0.x; v.y -= b0.y; v.z -= b0.z; v.w -= b0.w;
        ((float4*)(mem_s + (m * 3 + n) * MPAD))[c] = v;
    }
    __syncthreads();

    // GEMM: 192 threads (6 warps) = 96 col-pairs x 2 K-halves (kc warp-uniform)
    const bool is_gemm = (tid < 192);
    const int  q  = tid % 96;
    const int  kc = (tid / 96) & 1;
    const ulonglong2* mp0 = (const ulonglong2*)(mem_s + q * MPAD);
    const ulonglong2* mp1 = (const ulonglong2*)(mem_s + (q + 96) * MPAD);
    float* gdst = (kc == 0) ? gsm : part;
    const int d4b = kc * 32;

    // head-roll mapping (first 384 threads)
    const int rI = tid / ROWS;
    const int jj = tid % ROWS;

    // ---- prologue: head[0] (l' = l0-2, l0-1, full-K) + GEMM chunk 0 ----
    if (tid < 2 * ROWS) {
        int lp = l0 - 2 + rI;
        float v = 0.f;
        if (lp >= 0) {
            const ulonglong2* mpr = (const ulonglong2*)(mem_s + jj * MPAD);
            const ulonglong2* xp  = (const ulonglong2*)(xb + (size_t)lp * Dn);
            u64 p0 = 0ULL, p1 = 0ULL;
            #pragma unroll 8
            for (int d4 = 0; d4 < 64; ++d4) {
                ulonglong2 m  = mpr[d4];
                ulonglong2 xv = xp[d4];
                p0 = fma2(m.x, xv.x, p0);
                p1 = fma2(m.y, xv.y, p1);
            }
            v = hsum2(add2(p0, p1));
        }
        head[rI * ROWS + jj] = v;             // buffer 0 (combined values)
    }
    if (is_gemm) gemm_chunk(xs, mp0, mp1, gdst, d4b, q);
    __syncthreads();

    for (int ci = 0; ci < nc; ci++) {
        const int c0  = l0 + ci * CH;
        const int cur = ci & 1;
        float* hc = head + cur * (2 * ROWS);
        float* hn = head + (cur ^ 1) * (2 * ROWS);

        // ===== Phase A: stage xs_{i+1} + roll + argmax (+compaction) =====
        if (ci + 1 < nc) {
            for (int i = tid; i < CH * (Dn / 4); i += NT) {
                int r = i >> 6, c = i & 63;
                ((float4*)(xs + r * Dn))[c] =
                    ((const float4*)(xb + (size_t)(c0 + CH + r) * Dn))[c];
            }
        }
        if (tid < 2 * ROWS) {   // roll: head_next[rI] = combined G row (6+rI)
            int row = (6 + rI) * ROWS + jj;
            hn[rI * ROWS + jj] = gsm[row] + part[row];
        }
        {   // argmax: one (p, m) per thread; scores need Gd_n + G0 for n>=1
            int p    = tid >> 6;
            int m    = tid & 63;
            int m3   = m * 3;
            int lane = tid & 31;

            // combined-G fetch: row r (-2..5 here as p+n-2), col c
            float g0[3], gd[3];
            #pragma unroll
            for (int n = 0; n < 3; n++) {
                int r = p + n - 2;
                if (r < 0) {
                    g0[n] = hc[(r + 2) * ROWS + m3];
                    gd[n] = (n == 0) ? 0.f : hc[(r + 2) * ROWS + m3 + n];
                } else {
                    int o0 = r * ROWS + m3;
                    g0[n] = gsm[o0] + part[o0];
                    gd[n] = (n == 0) ? 0.f : (gsm[o0 + n] + part[o0 + n]);
                }
            }
            float s0 = g0[0] + bias_s[m3];
            float s1 = g0[1] + gd[1] + bias_s[m3 + 1];
            float s2 = g0[2] + gd[2] + bias_s[m3 + 2];
            int   bn = 0;
            float bv = s0;
            if (s1 > bv) { bv = s1; bn = 1; }
            if (s2 > bv) { bv = s2; bn = 2; }

            // warp-ballot compaction of active (bn != 0) delta-row offsets
            unsigned ball = __ballot_sync(0xffffffffu, bn != 0);
            int pos  = __popc(ball & ((1u << lane) - 1u));
            int half = m >> 5;
            if (bn != 0)
                best_s[p * SLOTS + half * 32 + pos] = (m3 + bn) * MPAD;
            if (lane == 0)
                cnt_s[p * 2 + half] = __popc(ball);
        }
        __syncthreads();

        // ===== Phase B: gather_i (10 warps) || GEMM_{i+1} (6 warps) =====
        if (!is_gemm) {
            int t = tid - 192;
            gather_one(mem_s, best_s, cnt_s, out, orow0 + c0, t);
            if (t < 192)
                gather_one(mem_s, best_s, cnt_s, out, orow0 + c0, t + 320);
        } else if (ci + 1 < nc) {
            gemm_chunk(xs, mp0, mp1, gdst, d4b, q);
        }
        __syncthreads();
    }
}

extern "C" void kernel_launch(void* const* d_in, const int* in_sizes, int n_in,
                              void* d_out, int out_size)
{
    const float* x    = (const float*)d_in[0];   // (4, 2048, 256) f32
    const float* mem  = (const float*)d_in[1];   // (64, 3, 256)   f32
    const float* bias = (const float*)d_in[2];   // (64, 3)        f32
    float* out        = (float*)d_out;           // (4, 2048, 256) f32

    (void)in_sizes; (void)n_in; (void)out_size;

    const int smem_bytes = SMEM_WORDS * (int)sizeof(float);   // 227152
    cudaFuncSetAttribute(pnm_kernel,
                         cudaFuncAttributeMaxDynamicSharedMemorySize,
                         smem_bytes);

    pnm_kernel<<<Bn * TILES_PER_B, NT, smem_bytes>>>(x, mem, bias, out);
}

// round 11
// speedup vs baseline: 1.0006x; 1.0006x over previous
#include <cuda_runtime.h>

// Problem constants
#define Bn 4
#define Ln 2048
#define Dn 256
#define SLOTS 64
#define ROWS 192          // SLOTS * 3
#define MPAD 260          // padded stride (words): conflict-free LDS.128
#define TILE 56           // 4 * 37 = 148 blocks = one full wave
#define CH 8              // positions per chunk
#define NT 512            // 16 warps: 3 GEMM + 13 consumer
#define GT 96             // GEMM threads (warps 0-2)
#define CT (NT - GT)      // 416 consumer threads (warps 3-15)
#define TILES_PER_B 37
#define GBUFW (CH * ROWS) // 1536 words per G buffer (full-K values)

// smem layout (words)
#define OFF_G    (ROWS * MPAD)                // 49920 : gbuf[2][8][192]
#define OFF_HEAD (OFF_G + 2 * GBUFW)          // +3072 : head[2][2][192]
#define OFF_BIAS (OFF_HEAD + 2 * 2 * ROWS)    // +768
#define OFF_BEST (OFF_BIAS + ROWS)            // +192  : best[8][64] (row*MPAD premult)
#define OFF_XS   (OFF_BEST + CH * SLOTS)      // +512  : xs[8][256] (GEMM-private)
#define SMEM_WORDS (OFF_XS + CH * Dn)         // +2048 -> 56512 words = 226048 B

// named barrier ids (0 = __syncthreads)
#define BAR_C 1           // 13 consumer warps (416 threads)
#define BAR_G 2           // 3 GEMM warps (96 threads)

typedef unsigned long long u64;

__device__ __forceinline__ void bar_named(int id, int cnt) {
    asm volatile("bar.sync %0, %1;" :: "r"(id), "r"(cnt) : "memory");
}
__device__ __forceinline__ u64 fma2(u64 a, u64 b, u64 c) {
    u64 d;
    asm("fma.rn.f32x2 %0, %1, %2, %3;" : "=l"(d) : "l"(a), "l"(b), "l"(c));
    return d;
}
__device__ __forceinline__ u64 add2(u64 a, u64 b) {
    u64 d;
    asm("add.rn.f32x2 %0, %1, %2;" : "=l"(d) : "l"(a), "l"(b));
    return d;
}
__device__ __forceinline__ float hsum2(u64 a) {
    float lo, hi;
    asm("mov.b64 {%0,%1}, %2;" : "=f"(lo), "=f"(hi) : "l"(a));
    return lo + hi;
}

// Full-K GEMM: 2 columns (q, q+96), 64 d4, 8 rows. x via warp-uniform broadcast.
__device__ __forceinline__ void gemm_full(
    const float* __restrict__ xsrc,
    const ulonglong2* __restrict__ mp0,
    const ulonglong2* __restrict__ mp1,
    float* __restrict__ gdst, int q)
{
    const ulonglong2* xp = (const ulonglong2*)xsrc;
    u64 a0[8], a1[8];
    #pragma unroll
    for (int r = 0; r < 8; r++) { a0[r] = 0ULL; a1[r] = 0ULL; }
    #pragma unroll 4
    for (int d4 = 0; d4 < 64; ++d4) {
        ulonglong2 m0 = mp0[d4];               // 4-phase LDS.128 (bank-perfect)
        ulonglong2 m1 = mp1[d4];
        #pragma unroll
        for (int r = 0; r < 8; r++) {
            ulonglong2 xv = xp[r * 64 + d4];   // broadcast
            a0[r] = fma2(m0.x, xv.x, a0[r]);
            a0[r] = fma2(m0.y, xv.y, a0[r]);
            a1[r] = fma2(m1.x, xv.x, a1[r]);
            a1[r] = fma2(m1.y, xv.y, a1[r]);
        }
    }
    #pragma unroll
    for (int r = 0; r < 8; r++) {
        gdst[r * ROWS + q]      = hsum2(a0[r]);
        gdst[r * ROWS + q + 96] = hsum2(a1[r]);
    }
}

// gather one (p, d4) item: out[p][d4*4..] = sum of 64 selected rows
__device__ __forceinline__ void gather_one(
    const float* __restrict__ mem_s, const int* __restrict__ best_s,
    float* __restrict__ out, size_t orow, int it)
{
    int p = it >> 6, d4 = it & 63;
    const int4* bp = (const int4*)(best_s + p * SLOTS);
    u64 ax[4] = {0ULL, 0ULL, 0ULL, 0ULL};
    u64 ay[4] = {0ULL, 0ULL, 0ULL, 0ULL};
    #pragma unroll
    for (int m4 = 0; m4 < 16; m4++) {
        int4 r4 = bp[m4];                      // warp-uniform broadcast
        int qq = m4 & 3;
        ulonglong2 v;
        v = ((const ulonglong2*)(mem_s + r4.x))[d4];
        ax[qq] = add2(ax[qq], v.x); ay[qq] = add2(ay[qq], v.y);
        v = ((const ulonglong2*)(mem_s + r4.y))[d4];
        ax[qq] = add2(ax[qq], v.x); ay[qq] = add2(ay[qq], v.y);
        v = ((const ulonglong2*)(mem_s + r4.z))[d4];
        ax[qq] = add2(ax[qq], v.x); ay[qq] = add2(ay[qq], v.y);
        v = ((const ulonglong2*)(mem_s + r4.w))[d4];
        ax[qq] = add2(ax[qq], v.x); ay[qq] = add2(ay[qq], v.y);
    }
    u64 s0 = add2(add2(ax[0], ax[1]), add2(ax[2], ax[3]));
    u64 s1 = add2(add2(ay[0], ay[1]), add2(ay[2], ay[3]));
    float x0, x1, y0, y1;
    asm("mov.b64 {%0,%1}, %2;" : "=f"(x0), "=f"(x1) : "l"(s0));
    asm("mov.b64 {%0,%1}, %2;" : "=f"(y0), "=f"(y1) : "l"(s1));
    ((float4*)(out + (orow + p) * Dn))[d4] = make_float4(x0, x1, y0, y1);
}

__global__ void __launch_bounds__(NT, 1)
pnm_kernel(const float* __restrict__ x,
           const float* __restrict__ mem,
           const float* __restrict__ bias,
           float* __restrict__ out)
{
    extern __shared__ float smem[];
    float* mem_s  = smem;                     // [ROWS][MPAD]
    float* gbuf   = smem + OFF_G;             // [2][8][192] full-K G values
    float* head   = smem + OFF_HEAD;          // [2][2][192]
    float* bias_s = smem + OFF_BIAS;          // [192]
    int*   best_s = (int*)(smem + OFF_BEST);  // [8][64]
    float* xs     = smem + OFF_XS;            // [8][256] (owned by GEMM warps in loop)

    const int tid  = threadIdx.x;
    const int b    = blockIdx.x / TILES_PER_B;
    const int l0   = (blockIdx.x % TILES_PER_B) * TILE;
    const int lend = (l0 + TILE < Ln) ? (l0 + TILE) : Ln;
    const int nc   = (lend - l0) / CH;        // 7 or 4

    const float* xb = x + (size_t)b * Ln * Dn;
    const size_t orow0 = (size_t)b * Ln;

    // ---- prologue 1: stage memory + bias + xs_0 ----
    for (int i = tid; i < ROWS * (Dn / 4); i += NT) {
        int r = i >> 6, c = i & 63;
        ((float4*)(mem_s + r * MPAD))[c] = ((const float4*)mem)[i];
    }
    if (tid < ROWS) bias_s[tid] = bias[tid];
    for (int i = tid; i < CH * (Dn / 4); i += NT) {
        int r = i >> 6, c = i & 63;
        ((float4*)(xs + r * Dn))[c] =
            ((const float4*)(xb + (size_t)(l0 + r) * Dn))[c];
    }
    __syncthreads();

    const bool is_g = (tid < GT);
    const int  q = tid;                       // GEMM col pair: q, q+96 (tid < 96)
    const ulonglong2* mp0 = (const ulonglong2*)(mem_s + (is_g ? q : 0) * MPAD);
    const ulonglong2* mp1 = (const ulonglong2*)(mem_s + ((is_g ? q : 0) + 96) * MPAD);

    // ---- prologue 2: G_0 (GEMM warps, from xs_0) + head seed (consumers) ----
    if (is_g) {
        gemm_full(xs, mp0, mp1, gbuf, q);
    } else {
        int t = tid - GT;                     // 0..415
        if (t < 2 * ROWS) {
            int rI = t / ROWS, jj = t % ROWS;
            int lp = l0 - 2 + rI;
            float v = 0.f;
            if (lp >= 0) {
                const ulonglong2* mpr = (const ulonglong2*)(mem_s + jj * MPAD);
                const ulonglong2* xp  = (const ulonglong2*)(xb + (size_t)lp * Dn);
                u64 p0 = 0ULL, p1 = 0ULL;
                #pragma unroll 8
                for (int d4 = 0; d4 < 64; ++d4) {
                    ulonglong2 m  = mpr[d4];
                    ulonglong2 xv = xp[d4];
                    p0 = fma2(m.x, xv.x, p0);
                    p1 = fma2(m.y, xv.y, p1);
                }
                v = hsum2(add2(p0, p1));
            }
            head[rI * ROWS + jj] = v;         // head buffer 0
        }
    }
    __syncthreads();

    // ---- prologue 3: stage xs_1 (all threads; consumed by GEMM in phase 0) ----
    if (nc > 1) {
        for (int i = tid; i < CH * (Dn / 4); i += NT) {
            int r = i >> 6, c = i & 63;
            ((float4*)(xs + r * Dn))[c] =
                ((const float4*)(xb + (size_t)(l0 + CH + r) * Dn))[c];
        }
    }
    __syncthreads();

    // ==================== main loop: ONE block barrier per chunk ====================
    for (int ci = 0; ci < nc; ci++) {
        const int cur = ci & 1;

        if (is_g) {
            // GEMM_{ci+1} into gbuf[cur^1]; then refill xs with xs_{ci+2}
            if (ci + 1 < nc) {
                gemm_full(xs, mp0, mp1, gbuf + (cur ^ 1) * GBUFW, q);
                bar_named(BAR_G, GT);         // all GEMM threads done reading xs
                if (ci + 2 < nc) {
                    const float* src = xb + (size_t)(l0 + (ci + 2) * CH) * Dn;
                    for (int i = tid; i < CH * (Dn / 4); i += GT) {
                        int r = i >> 6, c = i & 63;
                        // R10 bug was here: missing per-row offset (r * 64)
                        ((float4*)(xs + r * Dn))[c] =
                            ((const float4*)src)[r * 64 + c];
                    }
                }
            }
        } else {
            const int t = tid - GT;           // 0..415
            const float* gc = gbuf + cur * GBUFW;
            const float* hc = head + cur * (2 * ROWS);

            // roll: head[cur^1] <- G_ci rows 6,7 (history for argmax_{ci+1})
            if (t < 2 * ROWS) {
                int rI = t / ROWS, jj = t % ROWS;
                head[(cur ^ 1) * (2 * ROWS) + rI * ROWS + jj] =
                    gc[(6 + rI) * ROWS + jj];
            }
            // argmax_ci: 512 items over 416 threads
            #pragma unroll
            for (int ii = 0; ii < 2; ii++) {
                if (ii == 1 && t >= GT) break;
                int item = (ii == 0) ? t : (t + CT);
                int p  = item >> 6;
                int m3 = (item & 63) * 3;
                float sc[3];
                #pragma unroll
                for (int n = 0; n < 3; n++) {
                    int r   = p + n - 2;
                    int idx = m3 + n;
                    float g = (r < 0) ? hc[(r + 2) * ROWS + idx]
                                      : gc[r * ROWS + idx];
                    sc[n] = g + bias_s[idx];
                }
                int   bn = 0;
                float bv = sc[0];
                if (sc[1] > bv) { bv = sc[1]; bn = 1; }
                if (sc[2] > bv) { bv = sc[2]; bn = 2; }
                best_s[item] = (m3 + bn) * MPAD;
            }
            bar_named(BAR_C, CT);             // best_s ready for all consumers

            // gather_ci: 512 items over 416 threads
            gather_one(mem_s, best_s, out, orow0 + l0 + ci * CH, t);
            if (t < GT)
                gather_one(mem_s, best_s, out, orow0 + l0 + ci * CH, t + CT);
        }
        __syncthreads();
    }
}

extern "C" void kernel_launch(void* const* d_in, const int* in_sizes, int n_in,
                              void* d_out, int out_size)
{
    const float* x    = (const float*)d_in[0];   // (4, 2048, 256) f32
    const float* mem  = (const float*)d_in[1];   // (64, 3, 256)   f32
    const float* bias = (const float*)d_in[2];   // (64, 3)        f32
    float* out        = (float*)d_out;           // (4, 2048, 256) f32

    (void)in_sizes; (void)n_in; (void)out_size;

    const int smem_bytes = SMEM_WORDS * (int)sizeof(float);   // 226048
    cudaFuncSetAttribute(pnm_kernel,
                         cudaFuncAttributeMaxDynamicSharedMemorySize,
                         smem_bytes);

    pnm_kernel<<<Bn * TILES_PER_B, NT, smem_bytes>>>(x, mem, bias, out);
}

// round 12
// speedup vs baseline: 1.0419x; 1.0413x over previous
#include <cuda_runtime.h>

// Problem constants
#define Bn 4
#define Ln 2048
#define Dn 256
#define SLOTS 64
#define ROWS 192          // SLOTS * 3
#define MPAD 260          // padded stride (words): bank-stride 4 -> conflict-free LDS.128
#define TILE 56           // 4 * 37 = 148 blocks = one full wave
#define CH 8              // positions per chunk
#define NT 768            // 24 warps: 6 GEMM + 18 consumer
#define TILES_PER_B 37

// smem layout (words) — identical to R6 (226048 B)
#define OFF_GSM  (ROWS * MPAD)                // 49920 : gsm[8][192]  K-half 0
#define OFF_PART (OFF_GSM + CH * ROWS)        // +1536 : part[8][192] K-half 1
#define OFF_HEAD (OFF_PART + CH * ROWS)       // +1536 : head[2][2][192]
#define OFF_BIAS (OFF_HEAD + 2 * 2 * ROWS)    // +768
#define OFF_BEST (OFF_BIAS + ROWS)            // +192  : best[8][64] (row*MPAD premult)
#define OFF_XS   (OFF_BEST + CH * SLOTS)      // +512  : xs[8][256]
#define SMEM_WORDS (OFF_XS + CH * Dn)         // +2048 -> 56512 words = 226048 B

typedef unsigned long long u64;

__device__ __forceinline__ u64 fma2(u64 a, u64 b, u64 c) {
    u64 d;
    asm("fma.rn.f32x2 %0, %1, %2, %3;" : "=l"(d) : "l"(a), "l"(b), "l"(c));
    return d;
}
__device__ __forceinline__ u64 add2(u64 a, u64 b) {
    u64 d;
    asm("add.rn.f32x2 %0, %1, %2;" : "=l"(d) : "l"(a), "l"(b));
    return d;
}
__device__ __forceinline__ float hsum2(u64 a) {
    float lo, hi;
    asm("mov.b64 {%0,%1}, %2;" : "=f"(lo), "=f"(hi) : "l"(a));
    return lo + hi;
}

// GEMM slice: 2 columns (j0, j0+96), half-K (32 d4), 8 rows. x via broadcast LDS.
__device__ __forceinline__ void gemm_chunk(
    const float* __restrict__ xs,
    const ulonglong2* __restrict__ mp0,
    const ulonglong2* __restrict__ mp1,
    float* __restrict__ gdst, int d4b, int j0)
{
    const ulonglong2* xp = (const ulonglong2*)xs;
    u64 a0[8], a1[8];
    #pragma unroll
    for (int r = 0; r < 8; r++) { a0[r] = 0ULL; a1[r] = 0ULL; }
    #pragma unroll 4
    for (int d4 = d4b; d4 < d4b + 32; ++d4) {
        ulonglong2 m0 = mp0[d4];               // 4-phase LDS.128 (bank-perfect)
        ulonglong2 m1 = mp1[d4];
        #pragma unroll
        for (int r = 0; r < 8; r++) {
            ulonglong2 xv = xp[r * 64 + d4];   // warp-uniform broadcast LDS.128
            a0[r] = fma2(m0.x, xv.x, a0[r]);
            a0[r] = fma2(m0.y, xv.y, a0[r]);
            a1[r] = fma2(m1.x, xv.x, a1[r]);
            a1[r] = fma2(m1.y, xv.y, a1[r]);
        }
    }
    #pragma unroll
    for (int r = 0; r < 8; r++) {
        gdst[r * ROWS + j0]      = hsum2(a0[r]);
        gdst[r * ROWS + j0 + 96] = hsum2(a1[r]);
    }
}

// gather one (p, d4) item: out[p][d4*4..] = sum of 64 selected rows
__device__ __forceinline__ void gather_one(
    const float* __restrict__ mem_s, const int* __restrict__ best_s,
    float* __restrict__ out, size_t orow, int it)
{
    int p = it >> 6, d4 = it & 63;
    const int4* bp = (const int4*)(best_s + p * SLOTS);
    u64 ax[4] = {0ULL, 0ULL, 0ULL, 0ULL};
    u64 ay[4] = {0ULL, 0ULL, 0ULL, 0ULL};
    #pragma unroll
    for (int m4 = 0; m4 < 16; m4++) {
        int4 r4 = bp[m4];                      // warp-uniform broadcast
        int qq = m4 & 3;
        ulonglong2 v;
        v = ((const ulonglong2*)(mem_s + r4.x))[d4];
        ax[qq] = add2(ax[qq], v.x); ay[qq] = add2(ay[qq], v.y);
        v = ((const ulonglong2*)(mem_s + r4.y))[d4];
        ax[qq] = add2(ax[qq], v.x); ay[qq] = add2(ay[qq], v.y);
        v = ((const ulonglong2*)(mem_s + r4.z))[d4];
        ax[qq] = add2(ax[qq], v.x); ay[qq] = add2(ay[qq], v.y);
        v = ((const ulonglong2*)(mem_s + r4.w))[d4];
        ax[qq] = add2(ax[qq], v.x); ay[qq] = add2(ay[qq], v.y);
    }
    u64 s0 = add2(add2(ax[0], ax[1]), add2(ax[2], ax[3]));
    u64 s1 = add2(add2(ay[0], ay[1]), add2(ay[2], ay[3]));
    float x0, x1, y0, y1;
    asm("mov.b64 {%0,%1}, %2;" : "=f"(x0), "=f"(x1) : "l"(s0));
    asm("mov.b64 {%0,%1}, %2;" : "=f"(y0), "=f"(y1) : "l"(s1));
    ((float4*)(out + (orow + p) * Dn))[d4] = make_float4(x0, x1, y0, y1);
}

__global__ void __launch_bounds__(NT, 1)
pnm_kernel(const float* __restrict__ x,
           const float* __restrict__ mem,
           const float* __restrict__ bias,
           float* __restrict__ out)
{
    extern __shared__ float smem[];
    float* mem_s  = smem;                     // [ROWS][MPAD]
    float* gsm    = smem + OFF_GSM;           // [8][192]
    float* part   = smem + OFF_PART;          // [8][192]
    float* head   = smem + OFF_HEAD;          // [2][2][192]
    float* bias_s = smem + OFF_BIAS;          // [192]
    int*   best_s = (int*)(smem + OFF_BEST);  // [8][64]
    float* xs     = smem + OFF_XS;            // [8][256]

    const int tid  = threadIdx.x;
    const int b    = blockIdx.x / TILES_PER_B;
    const int l0   = (blockIdx.x % TILES_PER_B) * TILE;
    const int lend = (l0 + TILE < Ln) ? (l0 + TILE) : Ln;
    const int nc   = (lend - l0) / CH;        // 7 or 4

    const float* xb = x + (size_t)b * Ln * Dn;
    const size_t orow0 = (size_t)b * Ln;

    // ---- stage memory + bias + x chunk 0 ----
    for (int i = tid; i < ROWS * (Dn / 4); i += NT) {
        int r = i >> 6, c = i & 63;
        ((float4*)(mem_s + r * MPAD))[c] = ((const float4*)mem)[i];
    }
    if (tid < ROWS) bias_s[tid] = bias[tid];
    for (int i = tid; i < CH * (Dn / 4); i += NT) {
        int r = i >> 6, c = i & 63;
        ((float4*)(xs + r * Dn))[c] =
            ((const float4*)(xb + (size_t)(l0 + r) * Dn))[c];
    }
    __syncthreads();

    // GEMM: 192 threads (6 warps) = 96 col-pairs x 2 K-halves (kc warp-uniform)
    const bool is_gemm = (tid < 192);
    const int  q  = tid % 96;                 // col pair: j0=q, j1=q+96
    const int  kc = (tid / 96) & 1;           // 0/1 (valid for tid<192)
    const ulonglong2* mp0 = (const ulonglong2*)(mem_s + q * MPAD);
    const ulonglong2* mp1 = (const ulonglong2*)(mem_s + (q + 96) * MPAD);
    float* gdst = (kc == 0) ? gsm : part;
    const int d4b = kc * 32;

    // head-roll mapping (first 384 threads)
    const int rI = tid / ROWS;                // 0/1 for tid<384
    const int jj = tid % ROWS;

    // ---- prologue: head[0] (l' = l0-2, l0-1, full-K) + GEMM chunk 0 ----
    if (tid < 2 * ROWS) {
        int lp = l0 - 2 + rI;
        float v = 0.f;
        if (lp >= 0) {
            const ulonglong2* mpr = (const ulonglong2*)(mem_s + jj * MPAD);
            const ulonglong2* xp  = (const ulonglong2*)(xb + (size_t)lp * Dn);
            u64 p0 = 0ULL, p1 = 0ULL;
            #pragma unroll 8
            for (int d4 = 0; d4 < 64; ++d4) {
                ulonglong2 m  = mpr[d4];
                ulonglong2 xv = xp[d4];
                p0 = fma2(m.x, xv.x, p0);
                p1 = fma2(m.y, xv.y, p1);
            }
            v = hsum2(add2(p0, p1));
        }
        head[rI * ROWS + jj] = v;             // buffer 0
    }
    if (is_gemm) gemm_chunk(xs, mp0, mp1, gdst, d4b, q);
    __syncthreads();

    for (int ci = 0; ci < nc; ci++) {
        const int c0  = l0 + ci * CH;
        const int cur = ci & 1;
        float* hc = head + cur * (2 * ROWS);
        float* hn = head + (cur ^ 1) * (2 * ROWS);

        // ===== Phase A: stage xs_{i+1} + roll + argmax =====
        if (ci + 1 < nc) {
            for (int i = tid; i < CH * (Dn / 4); i += NT) {
                int r = i >> 6, c = i & 63;
                ((float4*)(xs + r * Dn))[c] =
                    ((const float4*)(xb + (size_t)(c0 + CH + r) * Dn))[c];
            }
        }
        if (tid < 2 * ROWS) {   // roll: head_next[rI] = G row (6+rI) = l' = c0+6+rI
            int row = (6 + rI) * ROWS + jj;
            hn[rI * ROWS + jj] = gsm[row] + part[row];
        }
        if (tid < CH * SLOTS) { // argmax: one (p, m) per thread (512 items)
            int p  = tid >> 6;
            int m3 = (tid & 63) * 3;
            float sc[3];
            #pragma unroll
            for (int n = 0; n < 3; n++) {
                int row = p + n - 2;
                int idx = m3 + n;
                float s;
                if (row < 0) {
                    s = hc[(row + 2) * ROWS + idx];
                } else {
                    int o = row * ROWS + idx;
                    s = gsm[o] + part[o];
                }
                sc[n] = s + bias_s[idx];
            }
            int   bn = 0;
            float bv = sc[0];
            if (sc[1] > bv) { bv = sc[1]; bn = 1; }
            if (sc[2] > bv) { bv = sc[2]; bn = 2; }
            best_s[tid] = (m3 + bn) * MPAD;
        }
        __syncthreads();

        // ===== Phase B: gather_i (18 warps, 1 item/thread) || GEMM_{i+1} (6 warps) =====
        if (!is_gemm) {
            int t = tid - 192;                 // 0..575
            if (t < CH * SLOTS)
                gather_one(mem_s, best_s, out, orow0 + c0, t);
        } else if (ci + 1 < nc) {
            gemm_chunk(xs, mp0, mp1, gdst, d4b, q);
        }
        __syncthreads();
    }
}

extern "C" void kernel_launch(void* const* d_in, const int* in_sizes, int n_in,
                              void* d_out, int out_size)
{
    const float* x    = (const float*)d_in[0];   // (4, 2048, 256) f32
    const float* mem  = (const float*)d_in[1];   // (64, 3, 256)   f32
    const float* bias = (const float*)d_in[2];   // (64, 3)        f32
    float* out        = (float*)d_out;           // (4, 2048, 256) f32

    (void)in_sizes; (void)n_in; (void)out_size;

    const int smem_bytes = SMEM_WORDS * (int)sizeof(float);   // 226048
    cudaFuncSetAttribute(pnm_kernel,
                         cudaFuncAttributeMaxDynamicSharedMemorySize,
                         smem_bytes);

    pnm_kernel<<<Bn * TILES_PER_B, NT, smem_bytes>>>(x, mem, bias, out);
}

// round 14
// speedup vs baseline: 1.1808x; 1.1333x over previous
#include <cuda_runtime.h>

// Problem constants
#define Bn 4
#define Ln 2048
#define Dn 256
#define SLOTS 64
#define ROWS 192          // SLOTS * 3
#define MPAD 260          // padded stride (words): conflict-free GEMM m-loads
#define TILE 56           // 4 * 37 = 148 blocks = one full wave
#define CH 8              // positions per chunk
#define NT 512            // 16 warps: 6 GEMM + 10 gather (all do argmax)
#define TILES_PER_B 37
#define GBUF (CH * ROWS)  // 1536 words per G buffer
#define XBUF (CH * Dn)    // 2048 words per x buffer

// smem layout (words)
#define OFF_GSM  (ROWS * MPAD)                 // 49920 : gsm[2][8][192]
#define OFF_BIAS (OFF_GSM + 2 * GBUF)          // +3072
#define OFF_BEST (OFF_BIAS + ROWS)             // +192  : best[2][512] ushort = 512 words
#define OFF_XS   (OFF_BEST + 512)              // xs[2][8][256]
#define SMEM_WORDS (OFF_XS + 2 * XBUF)         // 57792 words = 231168 B

typedef unsigned long long u64;
typedef unsigned int u32;

__device__ __forceinline__ void bar_gemm() {   // 6 GEMM warps only
    asm volatile("bar.sync 1, 192;" ::: "memory");
}
__device__ __forceinline__ u64 fma2(u64 a, u64 b, u64 c) {
    u64 d;
    asm("fma.rn.f32x2 %0, %1, %2, %3;" : "=l"(d) : "l"(a), "l"(b), "l"(c));
    return d;
}
__device__ __forceinline__ u64 add2(u64 a, u64 b) {
    u64 d;
    asm("add.rn.f32x2 %0, %1, %2;" : "=l"(d) : "l"(a), "l"(b));
    return d;
}
__device__ __forceinline__ float hsum2(u64 a) {
    float lo, hi;
    asm("mov.b64 {%0,%1}, %2;" : "=f"(lo), "=f"(hi) : "l"(a));
    return lo + hi;
}
__device__ __forceinline__ u32 smem_u32(const void* p) {
    u32 a;
    asm("{ .reg .u64 t; cvta.to.shared.u64 t, %1; cvt.u32.u64 %0, t; }"
        : "=r"(a) : "l"(p));
    return a;
}
__device__ __forceinline__ void cpasync16(u32 dst, const void* src) {
    asm volatile("cp.async.cg.shared.global [%0], [%1], 16;" :: "r"(dst), "l"(src));
}

// full-K dot of gmem x-row with smem mem-row (for head seeds)
__device__ __forceinline__ float dot_row(const float* xrow, const float* mrow) {
    const ulonglong2* mp = (const ulonglong2*)mrow;
    const ulonglong2* xp = (const ulonglong2*)xrow;
    u64 a0 = 0ULL, a1 = 0ULL;
    #pragma unroll 8
    for (int d4 = 0; d4 < 64; ++d4) {
        ulonglong2 m = mp[d4], xv = xp[d4];
        a0 = fma2(m.x, xv.x, a0);
        a1 = fma2(m.y, xv.y, a1);
    }
    return hsum2(add2(a0, a1));
}

// GEMM slice: 2 cols (j0, j0+96), K-half, 8 rows, x via broadcast LDS.
// kc1 writes gsm, bar, kc0 adds (combine folded in; no part buffer).
__device__ __forceinline__ void gemm_chunk(
    const float* __restrict__ xs,
    const ulonglong2* __restrict__ mp0,
    const ulonglong2* __restrict__ mp1,
    float* __restrict__ gdst, int d4b, int j0, int kc)
{
    const ulonglong2* xp = (const ulonglong2*)xs;
    u64 a0[8], a1[8];
    #pragma unroll
    for (int r = 0; r < 8; r++) { a0[r] = 0ULL; a1[r] = 0ULL; }
    #pragma unroll 4
    for (int d4 = d4b; d4 < d4b + 32; ++d4) {
        ulonglong2 m0 = mp0[d4];               // 4-phase LDS.128 (MPAD-padded)
        ulonglong2 m1 = mp1[d4];
        #pragma unroll
        for (int r = 0; r < 8; r++) {
            ulonglong2 xv = xp[r * 64 + d4];   // warp-uniform broadcast LDS.128
            a0[r] = fma2(m0.x, xv.x, a0[r]);
            a0[r] = fma2(m0.y, xv.y, a0[r]);
            a1[r] = fma2(m1.x, xv.x, a1[r]);
            a1[r] = fma2(m1.y, xv.y, a1[r]);
        }
    }
    if (kc == 1) {
        #pragma unroll
        for (int r = 0; r < 8; r++) {
            gdst[r * ROWS + j0]      = hsum2(a0[r]);
            gdst[r * ROWS + j0 + 96] = hsum2(a1[r]);
        }
    }
    bar_gemm();
    if (kc == 0) {
        #pragma unroll
        for (int r = 0; r < 8; r++) {
            gdst[r * ROWS + j0]      += hsum2(a0[r]);
            gdst[r * ROWS + j0 + 96] += hsum2(a1[r]);
        }
    }
}

// gather one (p, d4): sum 64 selected rows (ushort premult indices, broadcast)
__device__ __forceinline__ void gather_one(
    const float* __restrict__ mem_s, const unsigned short* __restrict__ bp,
    float* __restrict__ outp, int d4)
{
    const uint4* ip = (const uint4*)bp;        // 8 x uint4 = 64 ushorts
    u64 ax[4] = {0ULL, 0ULL, 0ULL, 0ULL};
    u64 ay[4] = {0ULL, 0ULL, 0ULL, 0ULL};
    #pragma unroll
    for (int g = 0; g < 8; g++) {
        uint4 w = ip[g];                       // warp-uniform broadcast
        int q = g & 3;
        ulonglong2 v;
        #define PNM_ROW(IDX) \
            v = ((const ulonglong2*)(mem_s + (IDX)))[d4]; \
            ax[q] = add2(ax[q], v.x); ay[q] = add2(ay[q], v.y);
        PNM_ROW(w.x & 0xFFFFu)  PNM_ROW(w.x >> 16)
        PNM_ROW(w.y & 0xFFFFu)  PNM_ROW(w.y >> 16)
        PNM_ROW(w.z & 0xFFFFu)  PNM_ROW(w.z >> 16)
        PNM_ROW(w.w & 0xFFFFu)  PNM_ROW(w.w >> 16)
        #undef PNM_ROW
    }
    u64 s0 = add2(add2(ax[0], ax[1]), add2(ax[2], ax[3]));
    u64 s1 = add2(add2(ay[0], ay[1]), add2(ay[2], ay[3]));
    float x0, x1, y0, y1;
    asm("mov.b64 {%0,%1}, %2;" : "=f"(x0), "=f"(x1) : "l"(s0));
    asm("mov.b64 {%0,%1}, %2;" : "=f"(y0), "=f"(y1) : "l"(s1));
    ((float4*)outp)[d4] = make_float4(x0, x1, y0, y1);
}

__global__ void __launch_bounds__(NT, 1)
pnm_kernel(const float* __restrict__ x,
           const float* __restrict__ mem,
           const float* __restrict__ bias,
           float* __restrict__ out)
{
    extern __shared__ float smem[];
    float* mem_s  = smem;                               // [ROWS][MPAD]
    float* gsm    = smem + OFF_GSM;                     // [2][8][192]
    float* bias_s = smem + OFF_BIAS;                    // [192]
    unsigned short* best_s = (unsigned short*)(smem + OFF_BEST); // [2][512]
    float* xs     = smem + OFF_XS;                      // [2][8][256]

    const int tid  = threadIdx.x;
    const int b    = blockIdx.x / TILES_PER_B;
    const int l0   = (blockIdx.x % TILES_PER_B) * TILE;
    const int lend = (l0 + TILE < Ln) ? (l0 + TILE) : Ln;
    const int nc   = (lend - l0) / CH;                  // 7 or 4 (always exact)

    const float* xb = x + (size_t)b * Ln * Dn;
    const size_t orow0 = (size_t)b * Ln;

    // ---- prologue 1: stage mem_s + bias + xs[0] (chunk0) + xs[1] (chunk1) ----
    for (int i = tid; i < ROWS * (Dn / 4); i += NT) {
        int r = i >> 6, c = i & 63;
        ((float4*)(mem_s + r * MPAD))[c] = ((const float4*)mem)[i];
    }
    if (tid < ROWS) bias_s[tid] = bias[tid];
    {
        int r = tid >> 6, c = tid & 63;
        ((float4*)(xs + r * Dn))[c] =
            ((const float4*)(xb + (size_t)(l0 + r) * Dn))[c];
        ((float4*)(xs + XBUF + r * Dn))[c] =
            ((const float4*)(xb + (size_t)(l0 + CH + r) * Dn))[c];
    }
    __syncthreads();

    // GEMM decomposition: 192 threads = 96 col-pairs x 2 K-halves (kc warp-uniform)
    const bool is_gemm = (tid < 192);
    const int  q  = tid % 96;
    const int  kc = (tid / 96) & 1;
    const ulonglong2* mp0 = (const ulonglong2*)(mem_s + q * MPAD);
    const ulonglong2* mp1 = (const ulonglong2*)(mem_s + (q + 96) * MPAD);
    const int d4b = kc * 32;

    // argmax identity (fixed across phases; h-regs live for tid<128)
    const int pa = tid >> 6;                   // position within chunk
    const int m3 = (tid & 63) * 3;
    float h0 = 0.f, h1 = 0.f;                  // boundary G values (p==0: n0,n1; p==1: n0)

    // ---- prologue 2: h seeds (tid<128) + GEMM chunk 0 -> gsm[0] ----
    if (tid < 128) {
        if (pa == 0) {
            if (l0 >= 2) h0 = dot_row(xb + (size_t)(l0 - 2) * Dn, mem_s + m3 * MPAD);
            if (l0 >= 1) h1 = dot_row(xb + (size_t)(l0 - 1) * Dn, mem_s + (m3 + 1) * MPAD);
        } else {
            if (l0 >= 1) h0 = dot_row(xb + (size_t)(l0 - 1) * Dn, mem_s + m3 * MPAD);
        }
    }
    if (is_gemm) gemm_chunk(xs, mp0, mp1, gsm, d4b, q, kc);
    __syncthreads();

    // ==================== single-barrier pipelined loop ====================
    // phase ci: argmax_ci | GEMM_{ci+1} | gather_{ci-1} | cp.async stage xs_{ci+2}
    for (int ci = 0; ci <= nc; ci++) {
        const int cur = ci & 1;

        // stage xs_{ci+2} into xs[cur] (async; GEMM this phase reads xs[cur^1])
        if (ci + 2 < nc) {
            int r = tid >> 6, c = tid & 63;
            cpasync16(smem_u32(xs + cur * XBUF + r * Dn + c * 4),
                      xb + (size_t)(l0 + (ci + 2) * CH + r) * Dn + c * 4);
        }

        // argmax_ci (all 512 threads, item = tid) -> best[cur]
        if (ci < nc) {
            const float* gc = gsm + cur * GBUF;
            float sc[3];
            #pragma unroll
            for (int n = 0; n < 3; n++) {
                int row = pa + n - 2;
                float g;
                if (row < 0) g = (n == 0) ? h0 : h1;   // only pa<=1 hits this
                else         g = gc[row * ROWS + m3 + n];
                sc[n] = g + bias_s[m3 + n];
            }
            int   bn = 0;
            float bv = sc[0];
            if (sc[1] > bv) { bv = sc[1]; bn = 1; }
            if (sc[2] > bv) { bv = sc[2]; bn = 2; }
            best_s[cur * NT + tid] = (unsigned short)((m3 + bn) * MPAD);
            // carry history for next chunk (rows 6,7 of current G)
            if (pa == 0) { h0 = gc[6 * ROWS + m3]; h1 = gc[7 * ROWS + m3 + 1]; }
            else if (pa == 1) { h0 = gc[7 * ROWS + m3]; }
        }

        if (is_gemm) {
            if (ci + 1 < nc)
                gemm_chunk(xs + (cur ^ 1) * XBUF, mp0, mp1,
                           gsm + (cur ^ 1) * GBUF, d4b, q, kc);
        } else if (ci >= 1) {
            // gather_{ci-1}: 512 items over 320 threads; reads best[cur^1]
            const unsigned short* bprev = best_s + (cur ^ 1) * NT;
            float* og = out + (orow0 + l0 + (size_t)(ci - 1) * CH) * Dn;
            int t = tid - 192;
            gather_one(mem_s, bprev + (t >> 6) * SLOTS, og + (size_t)(t >> 6) * Dn, t & 63);
            if (t < 192) {
                int t2 = t + 320;
                gather_one(mem_s, bprev + (t2 >> 6) * SLOTS, og + (size_t)(t2 >> 6) * Dn, t2 & 63);
            }
        }

        asm volatile("cp.async.wait_all;" ::: "memory");
        __syncthreads();
    }
}

extern "C" void kernel_launch(void* const* d_in, const int* in_sizes, int n_in,
                              void* d_out, int out_size)
{
    const float* x    = (const float*)d_in[0];   // (4, 2048, 256) f32
    const float* mem  = (const float*)d_in[1];   // (64, 3, 256)   f32
    const float* bias = (const float*)d_in[2];   // (64, 3)        f32
    float* out        = (float*)d_out;           // (4, 2048, 256) f32

    (void)in_sizes; (void)n_in; (void)out_size;

    const int smem_bytes = SMEM_WORDS * (int)sizeof(float);   // 231168
    cudaFuncSetAttribute(pnm_kernel,
                         cudaFuncAttributeMaxDynamicSharedMemorySize,
                         smem_bytes);

    pnm_kernel<<<Bn * TILES_PER_B, NT, smem_bytes>>>(x, mem, bias, out);
}